// round 5
// baseline (speedup 1.0000x reference)
#include <cuda_runtime.h>
#include <cuda_bf16.h>
#include <cstdint>

#define BATCH 32
#define DIM 1024
#define MLEN 512
#define NTILE 8                /* DIM / 128 */
#define NTRI 36                /* triu tile count */
#define TRIU_PER_B 524800      /* 1024*1025/2 */
#define INV2M (1.0f / 1024.0f)
#define ALPHA_C 0.4f
#define EPS_C 1e-5f
#define DIAG_V 0.01f           /* (1e-5)^0.4 exactly (fp32) */

#define NCH 32                 /* k-chunks of 16 */
#define RSTRIDE 48             /* smem row stride bytes (LDSM conflict-free) */
#define TILE_B (128 * RSTRIDE) /* 6144 */
#define STAGE_B (4 * TILE_B)   /* 24576: Ah, Al, Bh, Bl */
#define SMEM_MAIN (2 * STAGE_B)/* 49152 */

// ---- scratch (no device allocation allowed) -------------------------------
__device__ float g_diag[BATCH * DIM];
__device__ float g_rowsum[BATCH * DIM];
__device__ float g_rmean[BATCH * DIM];
__device__ float g_tot[BATCH];

#define LDSM4(R, ADDR)                                                         \
    asm volatile("ldmatrix.sync.aligned.m8n8.x4.shared.b16 {%0,%1,%2,%3}, [%4];" \
        : "=r"((R)[0]), "=r"((R)[1]), "=r"((R)[2]), "=r"((R)[3]) : "r"(ADDR))

#define MMA_BF16(D, A, B0, B1)                                                 \
    asm volatile(                                                              \
        "mma.sync.aligned.m16n8k16.row.col.f32.bf16.bf16.f32 "                 \
        "{%0,%1,%2,%3},{%4,%5,%6,%7},{%8,%9},{%0,%1,%2,%3};"                   \
        : "+f"((D)[0]), "+f"((D)[1]), "+f"((D)[2]), "+f"((D)[3])               \
        : "r"((A)[0]), "r"((A)[1]), "r"((A)[2]), "r"((A)[3]),                  \
          "r"(B0), "r"(B1))

__device__ __forceinline__ uint32_t smem_u32(const void* p) {
    uint32_t a;
    asm("{ .reg .u64 t; cvta.to.shared.u64 t, %1; cvt.u32.u64 %0, t; }"
        : "=r"(a) : "l"(p));
    return a;
}

// ---------------------------------------------------------------------------
// Kernel 1: diag[b,i] = sum_m x^2 / (2M); zero rowsum. One warp per row.
// ---------------------------------------------------------------------------
__global__ void k_diag(const float* __restrict__ x) {
    int row  = blockIdx.x * 8 + (threadIdx.x >> 5);
    int lane = threadIdx.x & 31;
    const float4* p = (const float4*)(x + (size_t)row * MLEN);
    float s = 0.f;
#pragma unroll
    for (int k = 0; k < 4; ++k) {
        float4 v = p[lane + 32 * k];
        s += v.x * v.x + v.y * v.y + v.z * v.z + v.w * v.w;
    }
#pragma unroll
    for (int o = 16; o; o >>= 1) s += __shfl_xor_sync(0xffffffffu, s, o);
    if (lane == 0) {
        g_diag[row]   = s * INV2M;
        g_rowsum[row] = 0.f;
    }
}

// ---------------------------------------------------------------------------
// Kernel 2: HMMA Gram (bf16 hi/lo x3) with in-kernel fp32->hi/lo conversion,
// ldmatrix fragment loads, direct predicated stores. 2 blocks/SM.
// ---------------------------------------------------------------------------
__global__ void __launch_bounds__(256, 2) k_main(const float* __restrict__ x,
                                                 float* __restrict__ out) {
    extern __shared__ char S[];
    __shared__ float rAcc[128], cAcc[128];

    int tid = threadIdx.x, wid = tid >> 5, lane = tid & 31;
    int g   = lane >> 2, tg = lane & 3;
    int wm  = wid >> 2, wn = wid & 3;

    int blk = blockIdx.x;
    int b = blk / NTRI;
    int t = blk - b * NTRI;
    int ti = 0;
    while (t >= NTILE - ti) { t -= NTILE - ti; ++ti; }
    int tj = ti + t;

    if (tid < 128) { rAcc[tid] = 0.f; cAcc[tid] = 0.f; }

    // loader role: threads 0..127 -> A tile rows, 128..255 -> B tile rows
    int lrow = tid & 127;
    int tsel = tid >> 7;
    const float* myrow = x + ((size_t)b * DIM +
                              (size_t)(tsel ? tj : ti) * 128 + lrow) * MLEN;
    char* dstH = S + (tsel ? 2 * TILE_B : 0) + lrow * RSTRIDE;  // hi tile
    // lo tile = dstH + TILE_B

    uint32_t sbase = smem_u32(S);
    // ldmatrix lane offsets
    uint32_t aOff = (uint32_t)((wm * 64 + ((lane >> 3) & 1) * 8 + (lane & 7)) * RSTRIDE
                               + (lane >> 4) * 16);
    uint32_t bOff = (uint32_t)((wn * 32 + ((lane >> 4) & 1) * 8 + (lane & 7)) * RSTRIDE
                               + ((lane >> 3) & 1) * 16);

    float acc[4][4][4];
#pragma unroll
    for (int i = 0; i < 4; ++i)
#pragma unroll
        for (int j = 0; j < 4; ++j)
#pragma unroll
            for (int k = 0; k < 4; ++k) acc[i][j][k] = 0.f;

    float4 pf[4];

    // convert 16 fp32 -> hi/lo bf16, store to stage st
    auto cvt_store = [&](int st) {
        unsigned short h16[16], l16[16];
        float e[16];
#pragma unroll
        for (int q = 0; q < 4; ++q) {
            e[q * 4 + 0] = pf[q].x; e[q * 4 + 1] = pf[q].y;
            e[q * 4 + 2] = pf[q].z; e[q * 4 + 3] = pf[q].w;
        }
#pragma unroll
        for (int k = 0; k < 16; ++k) {
            __nv_bfloat16 h = __float2bfloat16(e[k]);
            float hf = __bfloat162float(h);
            __nv_bfloat16 l = __float2bfloat16(e[k] - hf);
            h16[k] = *(unsigned short*)&h;
            l16[k] = *(unsigned short*)&l;
        }
        char* dh = dstH + st * STAGE_B;
        *(uint4*)(dh)               = *(uint4*)(h16);
        *(uint4*)(dh + 16)          = *(uint4*)(h16 + 8);
        *(uint4*)(dh + TILE_B)      = *(uint4*)(l16);
        *(uint4*)(dh + TILE_B + 16) = *(uint4*)(l16 + 8);
    };

    // prologue: chunk 0
#pragma unroll
    for (int q = 0; q < 4; ++q) pf[q] = ((const float4*)myrow)[q];
    cvt_store(0);
    __syncthreads();

#pragma unroll 1
    for (int kc = 0; kc < NCH; ++kc) {
        int st = kc & 1;
        if (kc + 1 < NCH) {
            const float4* src = (const float4*)(myrow + (kc + 1) * 16);
#pragma unroll
            for (int q = 0; q < 4; ++q) pf[q] = src[q];
        }
        uint32_t tAh = sbase + st * STAGE_B;
        uint32_t tAl = tAh + TILE_B;
        uint32_t tBh = tAh + 2 * TILE_B;
        uint32_t tBl = tAh + 3 * TILE_B;

        uint32_t bh[8], bl[8];
        LDSM4(bh,     tBh + bOff);
        LDSM4(bh + 4, tBh + bOff + 16 * RSTRIDE);
        LDSM4(bl,     tBl + bOff);
        LDSM4(bl + 4, tBl + bOff + 16 * RSTRIDE);

#pragma unroll
        for (int mt = 0; mt < 4; ++mt) {
            uint32_t ah[4], al[4];
            LDSM4(ah, tAh + aOff + mt * (16 * RSTRIDE));
            LDSM4(al, tAl + aOff + mt * (16 * RSTRIDE));
#pragma unroll
            for (int nt = 0; nt < 4; ++nt) {
                uint32_t b0h = bh[(nt >> 1) * 4 + (nt & 1) * 2];
                uint32_t b1h = bh[(nt >> 1) * 4 + (nt & 1) * 2 + 1];
                uint32_t b0l = bl[(nt >> 1) * 4 + (nt & 1) * 2];
                uint32_t b1l = bl[(nt >> 1) * 4 + (nt & 1) * 2 + 1];
                MMA_BF16(acc[mt][nt], ah, b0h, b1h);
                MMA_BF16(acc[mt][nt], ah, b0l, b1l);
                MMA_BF16(acc[mt][nt], al, b0h, b1h);
            }
        }
        __syncthreads();             // all warps done reading stage st
        if (kc + 1 < NCH) {
            cvt_store(st ^ 1);
            __syncthreads();         // next stage ready
        }
    }

    // ---- epilogue: dcov -> pow -> predicated direct store + sums -----------
    float diA[8], djB[8];
#pragma unroll
    for (int mt = 0; mt < 4; ++mt) {
        diA[mt * 2 + 0] = g_diag[b * DIM + ti * 128 + wm * 64 + mt * 16 + g];
        diA[mt * 2 + 1] = g_diag[b * DIM + ti * 128 + wm * 64 + mt * 16 + g + 8];
    }
#pragma unroll
    for (int nt = 0; nt < 4; ++nt) {
        djB[nt * 2 + 0] = g_diag[b * DIM + tj * 128 + wn * 32 + nt * 8 + tg * 2];
        djB[nt * 2 + 1] = g_diag[b * DIM + tj * 128 + wn * 32 + nt * 8 + tg * 2 + 1];
    }

    float* outb = out + (size_t)b * TRIU_PER_B;
    float r8[8], c8[8];
#pragma unroll
    for (int k = 0; k < 8; ++k) { r8[k] = 0.f; c8[k] = 0.f; }

#pragma unroll
    for (int mt = 0; mt < 4; ++mt) {
        int gi0 = ti * 128 + wm * 64 + mt * 16 + g;
        int gi1 = gi0 + 8;
        int rb0 = gi0 * DIM - (gi0 * (gi0 - 1)) / 2 - gi0;
        int rb1 = gi1 * DIM - (gi1 * (gi1 - 1)) / 2 - gi1;
#pragma unroll
        for (int nt = 0; nt < 4; ++nt) {
            int gj0 = tj * 128 + wn * 32 + nt * 8 + tg * 2;
            int gj1 = gj0 + 1;
            float v00, v01, v10, v11;
            {
                float gv = acc[mt][nt][0] * INV2M;
                float dc = fmaxf(diA[mt*2] + djB[nt*2] - 2.f*gv, 0.f) + EPS_C;
                v00 = (gi0 == gj0) ? DIAG_V : exp2f(ALPHA_C * __log2f(dc));
            }
            {
                float gv = acc[mt][nt][1] * INV2M;
                float dc = fmaxf(diA[mt*2] + djB[nt*2+1] - 2.f*gv, 0.f) + EPS_C;
                v01 = (gi0 == gj1) ? DIAG_V : exp2f(ALPHA_C * __log2f(dc));
            }
            {
                float gv = acc[mt][nt][2] * INV2M;
                float dc = fmaxf(diA[mt*2+1] + djB[nt*2] - 2.f*gv, 0.f) + EPS_C;
                v10 = (gi1 == gj0) ? DIAG_V : exp2f(ALPHA_C * __log2f(dc));
            }
            {
                float gv = acc[mt][nt][3] * INV2M;
                float dc = fmaxf(diA[mt*2+1] + djB[nt*2+1] - 2.f*gv, 0.f) + EPS_C;
                v11 = (gi1 == gj1) ? DIAG_V : exp2f(ALPHA_C * __log2f(dc));
            }
            if (gj0 >= gi0) outb[rb0 + gj0] = v00;
            if (gj1 >= gi0) outb[rb0 + gj1] = v01;
            if (gj0 >= gi1) outb[rb1 + gj0] = v10;
            if (gj1 >= gi1) outb[rb1 + gj1] = v11;
            r8[mt*2+0] += ((gj0 >= gi0) ? v00 : 0.f) + ((gj1 >= gi0) ? v01 : 0.f);
            r8[mt*2+1] += ((gj0 >= gi1) ? v10 : 0.f) + ((gj1 >= gi1) ? v11 : 0.f);
            c8[nt*2+0] += ((gj0 > gi0) ? v00 : 0.f) + ((gj0 > gi1) ? v10 : 0.f);
            c8[nt*2+1] += ((gj1 > gi0) ? v01 : 0.f) + ((gj1 > gi1) ? v11 : 0.f);
        }
    }

    // row partials: reduce over tg (lane bits 0,1)
#pragma unroll
    for (int k = 0; k < 8; ++k) {
        r8[k] += __shfl_xor_sync(0xffffffffu, r8[k], 1);
        r8[k] += __shfl_xor_sync(0xffffffffu, r8[k], 2);
    }
    if (tg == 0) {
#pragma unroll
        for (int k = 0; k < 8; ++k)
            atomicAdd(&rAcc[wm * 64 + (k >> 1) * 16 + g + (k & 1) * 8], r8[k]);
    }
    // col partials: reduce over g (lane bits 2,3,4)
#pragma unroll
    for (int k = 0; k < 8; ++k) {
        c8[k] += __shfl_xor_sync(0xffffffffu, c8[k], 4);
        c8[k] += __shfl_xor_sync(0xffffffffu, c8[k], 8);
        c8[k] += __shfl_xor_sync(0xffffffffu, c8[k], 16);
    }
    if (g == 0) {
#pragma unroll
        for (int k = 0; k < 8; ++k)
            atomicAdd(&cAcc[wn * 32 + (k >> 1) * 8 + tg * 2 + (k & 1)], c8[k]);
    }
    __syncthreads();

    if (tid < 128) {
        atomicAdd(&g_rowsum[b * DIM + ti * 128 + tid], rAcc[tid]);
        atomicAdd(&g_rowsum[b * DIM + tj * 128 + tid], cAcc[tid]);
    }
}

// ---------------------------------------------------------------------------
// Kernel 3: finalize per-batch means
// ---------------------------------------------------------------------------
__global__ void k_means() {
    int b = blockIdx.x, tid = threadIdx.x;
    __shared__ float red[256];
    float s = 0.f;
    for (int i = tid; i < DIM; i += 256) {
        float rs = g_rowsum[b * DIM + i];
        g_rmean[b * DIM + i] = rs * (1.0f / DIM);
        s += rs;
    }
    red[tid] = s;
    __syncthreads();
    for (int o = 128; o; o >>= 1) {
        if (tid < o) red[tid] += red[tid + o];
        __syncthreads();
    }
    if (tid == 0) g_tot[b] = red[0] * (1.0f / ((float)DIM * (float)DIM));
}

// ---------------------------------------------------------------------------
// Kernel 4: double-centering, paired rows (i, 1023-i) = exactly 1025 elems.
// ---------------------------------------------------------------------------
__global__ void k_center(float* __restrict__ out) {
    int u = blockIdx.x;                 // 0..511
    int b = blockIdx.y;
    int i1 = u, i2 = (DIM - 1) - u;
    int len1 = DIM - i1;
    int base1 = (i1 * (2 * DIM + 1 - i1)) >> 1;
    int base2 = (i2 * (2 * DIM + 1 - i2)) >> 1;
    const float* rm = g_rmean + b * DIM;
    float r1 = rm[i1], r2 = rm[i2], tt = g_tot[b];
    float* ob = out + (size_t)b * TRIU_PER_B;
    for (int t = threadIdx.x; t < DIM + 1; t += blockDim.x) {
        if (t < len1) {
            int p = base1 + t;
            ob[p] = ob[p] - r1 - rm[i1 + t] + tt;
        } else {
            int o = t - len1;
            int p = base2 + o;
            ob[p] = ob[p] - r2 - rm[i2 + o] + tt;
        }
    }
}

// ---------------------------------------------------------------------------
extern "C" void kernel_launch(void* const* d_in, const int* in_sizes, int n_in,
                              void* d_out, int out_size) {
    (void)in_sizes; (void)n_in; (void)out_size;
    const float* x = (const float*)d_in[0];
    float* out = (float*)d_out;

    cudaFuncSetAttribute(k_main, cudaFuncAttributeMaxDynamicSharedMemorySize,
                         SMEM_MAIN);

    k_diag<<<(BATCH * DIM) / 8, 256>>>(x);
    k_main<<<BATCH * NTRI, 256, SMEM_MAIN>>>(x, out);
    k_means<<<BATCH, 256>>>();
    k_center<<<dim3(DIM / 2, BATCH), 256>>>(out);
}

// round 6
// speedup vs baseline: 1.0890x; 1.0890x over previous
#include <cuda_runtime.h>
#include <cuda_bf16.h>
#include <cstdint>

#define BATCH 32
#define DIM 1024
#define MLEN 512
#define NTILE 8                /* DIM / 128 */
#define NTRI 36                /* triu tile count */
#define TRIU_PER_B 524800      /* 1024*1025/2 */
#define INV2M (1.0f / 1024.0f)
#define ALPHA_C 0.4f
#define EPS_C 1e-5f
#define DIAG_V 0.01f           /* (1e-5)^0.4 exactly (fp32) */

#define NCH 32                 /* k-chunks of 16 */
#define RSTRIDE 48             /* smem row stride bytes (LDSM conflict-free) */
#define TILE_B (128 * RSTRIDE) /* 6144 */
#define STAGE_B (4 * TILE_B)   /* 24576: Ah, Al, Bh, Bl */
#define NSTAGE 3
#define SMEM_MAIN (NSTAGE * STAGE_B)  /* 73728 */

// ---- scratch (no device allocation allowed) -------------------------------
__device__ __nv_bfloat16 g_hi[(size_t)BATCH * DIM * MLEN];
__device__ __nv_bfloat16 g_lo[(size_t)BATCH * DIM * MLEN];
__device__ float g_diag[BATCH * DIM];
__device__ float g_rowsum[BATCH * DIM];
__device__ float g_rmean[BATCH * DIM];
__device__ float g_tot[BATCH];

#define LDSM4(R, ADDR)                                                         \
    asm volatile("ldmatrix.sync.aligned.m8n8.x4.shared.b16 {%0,%1,%2,%3}, [%4];" \
        : "=r"((R)[0]), "=r"((R)[1]), "=r"((R)[2]), "=r"((R)[3]) : "r"(ADDR))

#define MMA_BF16(D, A, B0, B1)                                                 \
    asm volatile(                                                              \
        "mma.sync.aligned.m16n8k16.row.col.f32.bf16.bf16.f32 "                 \
        "{%0,%1,%2,%3},{%4,%5,%6,%7},{%8,%9},{%0,%1,%2,%3};"                   \
        : "+f"((D)[0]), "+f"((D)[1]), "+f"((D)[2]), "+f"((D)[3])               \
        : "r"((A)[0]), "r"((A)[1]), "r"((A)[2]), "r"((A)[3]),                  \
          "r"(B0), "r"(B1))

#define CP16(dst, src)                                                         \
    asm volatile("cp.async.cg.shared.global [%0], [%1], 16;"                   \
                 :: "r"(dst), "l"(src))
#define CP_COMMIT() asm volatile("cp.async.commit_group;" ::: "memory")
#define CP_WAIT(n)  asm volatile("cp.async.wait_group %0;" :: "n"(n) : "memory")

__device__ __forceinline__ uint32_t smem_u32(const void* p) {
    uint32_t a;
    asm("{ .reg .u64 t; cvta.to.shared.u64 t, %1; cvt.u32.u64 %0, t; }"
        : "=r"(a) : "l"(p));
    return a;
}

// ---------------------------------------------------------------------------
// Kernel 1: split fp32 -> bf16 hi/lo, fused diag + rowsum zero. 1 warp/row.
// ---------------------------------------------------------------------------
__global__ void k_split(const float* __restrict__ x) {
    int row  = blockIdx.x * 8 + (threadIdx.x >> 5);
    int lane = threadIdx.x & 31;
    const float4* p = (const float4*)(x + (size_t)row * MLEN);
    __nv_bfloat16* ph = g_hi + (size_t)row * MLEN;
    __nv_bfloat16* pl = g_lo + (size_t)row * MLEN;
    float s = 0.f;
#pragma unroll
    for (int it = 0; it < 4; ++it) {
        int idx = lane + 32 * it;
        float4 v = p[idx];
        s += v.x * v.x + v.y * v.y + v.z * v.z + v.w * v.w;
        __nv_bfloat16 hh[4], ll[4];
        float e[4] = {v.x, v.y, v.z, v.w};
#pragma unroll
        for (int k = 0; k < 4; ++k) {
            hh[k] = __float2bfloat16(e[k]);
            ll[k] = __float2bfloat16(e[k] - __bfloat162float(hh[k]));
        }
        *(uint2*)(ph + idx * 4) = *(uint2*)hh;
        *(uint2*)(pl + idx * 4) = *(uint2*)ll;
    }
#pragma unroll
    for (int o = 16; o; o >>= 1) s += __shfl_xor_sync(0xffffffffu, s, o);
    if (lane == 0) {
        g_diag[row]   = s * INV2M;
        g_rowsum[row] = 0.f;
    }
}

// ---------------------------------------------------------------------------
// Kernel 2: HMMA Gram (bf16 hi/lo x3), cp.async 3-stage pipeline, ldmatrix,
// direct predicated stores. 2 blocks/SM.
// ---------------------------------------------------------------------------
__global__ void __launch_bounds__(256, 2) k_main(float* __restrict__ out) {
    extern __shared__ char S[];
    __shared__ float rAcc[128], cAcc[128];

    int tid = threadIdx.x, wid = tid >> 5, lane = tid & 31;
    int g   = lane >> 2, tg = lane & 3;
    int wm  = wid >> 2, wn = wid & 3;

    int blk = blockIdx.x;
    int b = blk / NTRI;
    int t = blk - b * NTRI;
    int ti = 0;
    while (t >= NTILE - ti) { t -= NTILE - ti; ++ti; }
    int tj = ti + t;

    if (tid < 128) { rAcc[tid] = 0.f; cAcc[tid] = 0.f; }

    // loader role: threads 0..127 -> A-tile row, 128..255 -> B-tile row.
    // Each thread owns hi+lo of its row: 4 x cp.async(16B) per chunk.
    int lrow = tid & 127;
    int tsel = tid >> 7;
    size_t rowoff = ((size_t)b * DIM + (size_t)(tsel ? tj : ti) * 128 + lrow) * MLEN;
    const char* srcH = (const char*)(g_hi + rowoff);
    const char* srcL = (const char*)(g_lo + rowoff);

    uint32_t sbase = smem_u32(S);
    uint32_t dH = sbase + (tsel ? 2 * TILE_B : 0) + (uint32_t)lrow * RSTRIDE;
    uint32_t dL = dH + TILE_B;

    auto issue = [&](int kc, int st) {
        uint32_t o = (uint32_t)st * STAGE_B;
        int go = kc * 32;               // 16 bf16 = 32 bytes per row
        CP16(dH + o,      srcH + go);
        CP16(dH + o + 16, srcH + go + 16);
        CP16(dL + o,      srcL + go);
        CP16(dL + o + 16, srcL + go + 16);
        CP_COMMIT();
    };

    // ldmatrix lane offsets
    uint32_t aOff = (uint32_t)((wm * 64 + ((lane >> 3) & 1) * 8 + (lane & 7)) * RSTRIDE
                               + (lane >> 4) * 16);
    uint32_t bOff = (uint32_t)((wn * 32 + ((lane >> 4) & 1) * 8 + (lane & 7)) * RSTRIDE
                               + ((lane >> 3) & 1) * 16);

    float acc[4][4][4];
#pragma unroll
    for (int i = 0; i < 4; ++i)
#pragma unroll
        for (int j = 0; j < 4; ++j)
#pragma unroll
            for (int k = 0; k < 4; ++k) acc[i][j][k] = 0.f;

    issue(0, 0);
    issue(1, 1);

#pragma unroll 1
    for (int kc = 0; kc < NCH; ++kc) {
        if (kc == NCH - 1) { CP_WAIT(0); } else { CP_WAIT(1); }
        __syncthreads();                 // chunk kc visible; stage (kc+2)%3 free
        if (kc + 2 < NCH) issue(kc + 2, (kc + 2) % NSTAGE);

        uint32_t tAh = sbase + (uint32_t)(kc % NSTAGE) * STAGE_B;
        uint32_t tAl = tAh + TILE_B;
        uint32_t tBh = tAh + 2 * TILE_B;
        uint32_t tBl = tAh + 3 * TILE_B;

        uint32_t bh[8], bl[8];
        LDSM4(bh,     tBh + bOff);
        LDSM4(bh + 4, tBh + bOff + 16 * RSTRIDE);
        LDSM4(bl,     tBl + bOff);
        LDSM4(bl + 4, tBl + bOff + 16 * RSTRIDE);

#pragma unroll
        for (int mt = 0; mt < 4; ++mt) {
            uint32_t ah[4], al[4];
            LDSM4(ah, tAh + aOff + mt * (16 * RSTRIDE));
            LDSM4(al, tAl + aOff + mt * (16 * RSTRIDE));
#pragma unroll
            for (int nt = 0; nt < 4; ++nt) {
                uint32_t b0h = bh[(nt >> 1) * 4 + (nt & 1) * 2];
                uint32_t b1h = bh[(nt >> 1) * 4 + (nt & 1) * 2 + 1];
                uint32_t b0l = bl[(nt >> 1) * 4 + (nt & 1) * 2];
                uint32_t b1l = bl[(nt >> 1) * 4 + (nt & 1) * 2 + 1];
                MMA_BF16(acc[mt][nt], ah, b0h, b1h);
                MMA_BF16(acc[mt][nt], ah, b0l, b1l);
                MMA_BF16(acc[mt][nt], al, b0h, b1h);
            }
        }
    }

    // ---- epilogue: dcov -> pow -> predicated direct store + sums -----------
    float diA[8], djB[8];
#pragma unroll
    for (int mt = 0; mt < 4; ++mt) {
        diA[mt * 2 + 0] = g_diag[b * DIM + ti * 128 + wm * 64 + mt * 16 + g];
        diA[mt * 2 + 1] = g_diag[b * DIM + ti * 128 + wm * 64 + mt * 16 + g + 8];
    }
#pragma unroll
    for (int nt = 0; nt < 4; ++nt) {
        djB[nt * 2 + 0] = g_diag[b * DIM + tj * 128 + wn * 32 + nt * 8 + tg * 2];
        djB[nt * 2 + 1] = g_diag[b * DIM + tj * 128 + wn * 32 + nt * 8 + tg * 2 + 1];
    }

    float* outb = out + (size_t)b * TRIU_PER_B;
    float r8[8], c8[8];
#pragma unroll
    for (int k = 0; k < 8; ++k) { r8[k] = 0.f; c8[k] = 0.f; }

#pragma unroll
    for (int mt = 0; mt < 4; ++mt) {
        int gi0 = ti * 128 + wm * 64 + mt * 16 + g;
        int gi1 = gi0 + 8;
        int rb0 = gi0 * DIM - (gi0 * (gi0 - 1)) / 2 - gi0;
        int rb1 = gi1 * DIM - (gi1 * (gi1 - 1)) / 2 - gi1;
#pragma unroll
        for (int nt = 0; nt < 4; ++nt) {
            int gj0 = tj * 128 + wn * 32 + nt * 8 + tg * 2;
            int gj1 = gj0 + 1;
            float v00, v01, v10, v11;
            {
                float gv = acc[mt][nt][0] * INV2M;
                float dc = fmaxf(diA[mt*2] + djB[nt*2] - 2.f*gv, 0.f) + EPS_C;
                v00 = (gi0 == gj0) ? DIAG_V : exp2f(ALPHA_C * __log2f(dc));
            }
            {
                float gv = acc[mt][nt][1] * INV2M;
                float dc = fmaxf(diA[mt*2] + djB[nt*2+1] - 2.f*gv, 0.f) + EPS_C;
                v01 = (gi0 == gj1) ? DIAG_V : exp2f(ALPHA_C * __log2f(dc));
            }
            {
                float gv = acc[mt][nt][2] * INV2M;
                float dc = fmaxf(diA[mt*2+1] + djB[nt*2] - 2.f*gv, 0.f) + EPS_C;
                v10 = (gi1 == gj0) ? DIAG_V : exp2f(ALPHA_C * __log2f(dc));
            }
            {
                float gv = acc[mt][nt][3] * INV2M;
                float dc = fmaxf(diA[mt*2+1] + djB[nt*2+1] - 2.f*gv, 0.f) + EPS_C;
                v11 = (gi1 == gj1) ? DIAG_V : exp2f(ALPHA_C * __log2f(dc));
            }
            if (gj0 >= gi0) outb[rb0 + gj0] = v00;
            if (gj1 >= gi0) outb[rb0 + gj1] = v01;
            if (gj0 >= gi1) outb[rb1 + gj0] = v10;
            if (gj1 >= gi1) outb[rb1 + gj1] = v11;
            r8[mt*2+0] += ((gj0 >= gi0) ? v00 : 0.f) + ((gj1 >= gi0) ? v01 : 0.f);
            r8[mt*2+1] += ((gj0 >= gi1) ? v10 : 0.f) + ((gj1 >= gi1) ? v11 : 0.f);
            c8[nt*2+0] += ((gj0 > gi0) ? v00 : 0.f) + ((gj0 > gi1) ? v10 : 0.f);
            c8[nt*2+1] += ((gj1 > gi0) ? v01 : 0.f) + ((gj1 > gi1) ? v11 : 0.f);
        }
    }

    // row partials: reduce over tg (lane bits 0,1)
#pragma unroll
    for (int k = 0; k < 8; ++k) {
        r8[k] += __shfl_xor_sync(0xffffffffu, r8[k], 1);
        r8[k] += __shfl_xor_sync(0xffffffffu, r8[k], 2);
    }
    if (tg == 0) {
#pragma unroll
        for (int k = 0; k < 8; ++k)
            atomicAdd(&rAcc[wm * 64 + (k >> 1) * 16 + g + (k & 1) * 8], r8[k]);
    }
    // col partials: reduce over g (lane bits 2,3,4)
#pragma unroll
    for (int k = 0; k < 8; ++k) {
        c8[k] += __shfl_xor_sync(0xffffffffu, c8[k], 4);
        c8[k] += __shfl_xor_sync(0xffffffffu, c8[k], 8);
        c8[k] += __shfl_xor_sync(0xffffffffu, c8[k], 16);
    }
    if (g == 0) {
#pragma unroll
        for (int k = 0; k < 8; ++k)
            atomicAdd(&cAcc[wn * 32 + (k >> 1) * 8 + tg * 2 + (k & 1)], c8[k]);
    }
    __syncthreads();

    if (tid < 128) {
        atomicAdd(&g_rowsum[b * DIM + ti * 128 + tid], rAcc[tid]);
        atomicAdd(&g_rowsum[b * DIM + tj * 128 + tid], cAcc[tid]);
    }
}

// ---------------------------------------------------------------------------
// Kernel 3: finalize per-batch means
// ---------------------------------------------------------------------------
__global__ void k_means() {
    int b = blockIdx.x, tid = threadIdx.x;
    __shared__ float red[256];
    float s = 0.f;
    for (int i = tid; i < DIM; i += 256) {
        float rs = g_rowsum[b * DIM + i];
        g_rmean[b * DIM + i] = rs * (1.0f / DIM);
        s += rs;
    }
    red[tid] = s;
    __syncthreads();
    for (int o = 128; o; o >>= 1) {
        if (tid < o) red[tid] += red[tid + o];
        __syncthreads();
    }
    if (tid == 0) g_tot[b] = red[0] * (1.0f / ((float)DIM * (float)DIM));
}

// ---------------------------------------------------------------------------
// Kernel 4: flat float4 double-centering with sqrt-based row inversion.
// ---------------------------------------------------------------------------
__device__ __forceinline__ int rb_of(int i) { return (i * (2 * DIM + 1 - i)) >> 1; }

__global__ void k_center(float* __restrict__ out) {
    int idx = blockIdx.x * blockDim.x + threadIdx.x;   // float4 index
    int b  = idx / (TRIU_PER_B / 4);
    int p  = (idx - b * (TRIU_PER_B / 4)) * 4;
    float arg = (float)(4198401 - 8 * p);
    int i = (int)((2049.0f - sqrtf(arg)) * 0.5f);
    if (i < 0) i = 0;
    if (i > DIM - 1) i = DIM - 1;
    while (i > 0 && rb_of(i) > p) --i;
    while (rb_of(i + 1) <= p) ++i;

    const float* rm = g_rmean + b * DIM;
    float tt = g_tot[b];
    float* ptr = out + (size_t)b * TRIU_PER_B + p;
    float4 v = *(float4*)ptr;
    float e[4] = {v.x, v.y, v.z, v.w};
    int ii = i;
#pragma unroll
    for (int k = 0; k < 4; ++k) {
        while (rb_of(ii + 1) <= p + k) ++ii;
        int j = p + k - rb_of(ii) + ii;
        e[k] = e[k] - rm[ii] - rm[j] + tt;
    }
    v.x = e[0]; v.y = e[1]; v.z = e[2]; v.w = e[3];
    *(float4*)ptr = v;
}

// ---------------------------------------------------------------------------
extern "C" void kernel_launch(void* const* d_in, const int* in_sizes, int n_in,
                              void* d_out, int out_size) {
    (void)in_sizes; (void)n_in; (void)out_size;
    const float* x = (const float*)d_in[0];
    float* out = (float*)d_out;

    cudaFuncSetAttribute(k_main, cudaFuncAttributeMaxDynamicSharedMemorySize,
                         SMEM_MAIN);

    k_split<<<(BATCH * DIM) / 8, 256>>>(x);
    k_main<<<BATCH * NTRI, 256, SMEM_MAIN>>>(out);
    k_means<<<BATCH, 256>>>();
    k_center<<<(BATCH * TRIU_PER_B / 4) / 256, 256>>>(out);
}

// round 7
// speedup vs baseline: 1.6994x; 1.5605x over previous
#include <cuda_runtime.h>
#include <cuda_fp16.h>
#include <cstdint>

#define BATCH 32
#define DIM 1024
#define MLEN 512
#define NTILE 8                /* DIM / 128 */
#define NTRI 36                /* triu tile count */
#define TRIU_PER_B 524800      /* 1024*1025/2 */
#define INV2M (1.0f / 1024.0f)
#define ALPHA_C 0.4f
#define EPS_C 1e-5f
#define DIAG_V 0.01f           /* (1e-5)^0.4 exactly (fp32) */

#define NCH 32                 /* k-chunks of 16 */
#define RSTRIDE 48             /* smem row stride bytes (LDSM conflict-free) */
#define TILE_B (128 * RSTRIDE) /* 6144 */
#define STAGE_B (2 * TILE_B)   /* 12288: Ah, Bh */
#define NSTAGE 3
#define SMEM_MAIN (NSTAGE * STAGE_B)  /* 36864 */

// ---- scratch (no device allocation allowed) -------------------------------
__device__ __half g_h[(size_t)BATCH * DIM * MLEN];
__device__ float g_diag[BATCH * DIM];
__device__ float g_rowsum[BATCH * DIM];
__device__ float g_rmean[BATCH * DIM];
__device__ float g_tot[BATCH];

#define LDSM4(R, ADDR)                                                         \
    asm volatile("ldmatrix.sync.aligned.m8n8.x4.shared.b16 {%0,%1,%2,%3}, [%4];" \
        : "=r"((R)[0]), "=r"((R)[1]), "=r"((R)[2]), "=r"((R)[3]) : "r"(ADDR))

#define MMA_F16(D, A, B0, B1)                                                  \
    asm volatile(                                                              \
        "mma.sync.aligned.m16n8k16.row.col.f32.f16.f16.f32 "                   \
        "{%0,%1,%2,%3},{%4,%5,%6,%7},{%8,%9},{%0,%1,%2,%3};"                   \
        : "+f"((D)[0]), "+f"((D)[1]), "+f"((D)[2]), "+f"((D)[3])               \
        : "r"((A)[0]), "r"((A)[1]), "r"((A)[2]), "r"((A)[3]),                  \
          "r"(B0), "r"(B1))

#define CP16(dst, src)                                                         \
    asm volatile("cp.async.cg.shared.global [%0], [%1], 16;"                   \
                 :: "r"(dst), "l"(src))
#define CP_COMMIT() asm volatile("cp.async.commit_group;" ::: "memory")
#define CP_WAIT(n)  asm volatile("cp.async.wait_group %0;" :: "n"(n) : "memory")

__device__ __forceinline__ uint32_t smem_u32(const void* p) {
    uint32_t a;
    asm("{ .reg .u64 t; cvta.to.shared.u64 t, %1; cvt.u32.u64 %0, t; }"
        : "=r"(a) : "l"(p));
    return a;
}

// ---------------------------------------------------------------------------
// Kernel 1: fp32 -> fp16 convert, fused diag + rowsum zero. 1 warp/row.
// ---------------------------------------------------------------------------
__global__ void k_half(const float* __restrict__ x) {
    int row  = blockIdx.x * 8 + (threadIdx.x >> 5);
    int lane = threadIdx.x & 31;
    const float4* p = (const float4*)(x + (size_t)row * MLEN);
    __half* ph = g_h + (size_t)row * MLEN;
    float s = 0.f;
#pragma unroll
    for (int it = 0; it < 4; ++it) {
        int idx = lane + 32 * it;
        float4 v = p[idx];
        s += v.x * v.x + v.y * v.y + v.z * v.z + v.w * v.w;
        __half hh[4];
        hh[0] = __float2half(v.x); hh[1] = __float2half(v.y);
        hh[2] = __float2half(v.z); hh[3] = __float2half(v.w);
        *(uint2*)(ph + idx * 4) = *(uint2*)hh;
    }
#pragma unroll
    for (int o = 16; o; o >>= 1) s += __shfl_xor_sync(0xffffffffu, s, o);
    if (lane == 0) {
        g_diag[row]   = s * INV2M;
        g_rowsum[row] = 0.f;
    }
}

// ---------------------------------------------------------------------------
// Kernel 2: fp16 single-product HMMA Gram, cp.async 3-stage pipeline,
// ldmatrix, triu fragment skip, direct predicated stores. 2 blocks/SM.
// ---------------------------------------------------------------------------
__global__ void __launch_bounds__(256, 2) k_main(float* __restrict__ out) {
    extern __shared__ char S[];
    __shared__ float rAcc[128], cAcc[128];

    int tid = threadIdx.x, wid = tid >> 5, lane = tid & 31;
    int g   = lane >> 2, tg = lane & 3;
    int wm  = wid >> 2, wn = wid & 3;

    int blk = blockIdx.x;
    int b = blk / NTRI;
    int t = blk - b * NTRI;
    int ti = 0;
    while (t >= NTILE - ti) { t -= NTILE - ti; ++ti; }
    int tj = ti + t;

    if (tid < 128) { rAcc[tid] = 0.f; cAcc[tid] = 0.f; }

    // fragment-skip mask (warp-uniform): diag tile & fragment fully below diag
    bool diagT = (ti == tj);
    bool skipF[4][4];
#pragma unroll
    for (int mt = 0; mt < 4; ++mt)
#pragma unroll
        for (int nt = 0; nt < 4; ++nt)
            skipF[mt][nt] = diagT && (wn * 32 + nt * 8 + 7 < wm * 64 + mt * 16);

    // loader role: threads 0..127 -> A-tile row, 128..255 -> B-tile row.
    int lrow = tid & 127;
    int tsel = tid >> 7;
    size_t rowoff = ((size_t)b * DIM + (size_t)(tsel ? tj : ti) * 128 + lrow) * MLEN;
    const char* srcH = (const char*)(g_h + rowoff);

    uint32_t sbase = smem_u32(S);
    uint32_t dH = sbase + (tsel ? TILE_B : 0) + (uint32_t)lrow * RSTRIDE;

    auto issue = [&](int kc, int st) {
        uint32_t o = (uint32_t)st * STAGE_B;
        int go = kc * 32;               // 16 fp16 = 32 bytes per row
        CP16(dH + o,      srcH + go);
        CP16(dH + o + 16, srcH + go + 16);
        CP_COMMIT();
    };

    // ldmatrix lane offsets
    uint32_t aOff = (uint32_t)((wm * 64 + ((lane >> 3) & 1) * 8 + (lane & 7)) * RSTRIDE
                               + (lane >> 4) * 16);
    uint32_t bOff = (uint32_t)((wn * 32 + ((lane >> 4) & 1) * 8 + (lane & 7)) * RSTRIDE
                               + ((lane >> 3) & 1) * 16);

    float acc[4][4][4];
#pragma unroll
    for (int i = 0; i < 4; ++i)
#pragma unroll
        for (int j = 0; j < 4; ++j)
#pragma unroll
            for (int k = 0; k < 4; ++k) acc[i][j][k] = 0.f;

    issue(0, 0);
    issue(1, 1);

#pragma unroll 1
    for (int kc = 0; kc < NCH; ++kc) {
        if (kc == NCH - 1) { CP_WAIT(0); } else { CP_WAIT(1); }
        __syncthreads();                 // chunk kc visible; old stage free
        if (kc + 2 < NCH) issue(kc + 2, (kc + 2) % NSTAGE);

        uint32_t tAh = sbase + (uint32_t)(kc % NSTAGE) * STAGE_B;
        uint32_t tBh = tAh + TILE_B;

        uint32_t bh[8];
        LDSM4(bh,     tBh + bOff);
        LDSM4(bh + 4, tBh + bOff + 16 * RSTRIDE);

#pragma unroll
        for (int mt = 0; mt < 4; ++mt) {
            uint32_t ah[4];
            LDSM4(ah, tAh + aOff + mt * (16 * RSTRIDE));
#pragma unroll
            for (int nt = 0; nt < 4; ++nt) {
                if (skipF[mt][nt]) continue;
                uint32_t b0 = bh[(nt >> 1) * 4 + (nt & 1) * 2];
                uint32_t b1 = bh[(nt >> 1) * 4 + (nt & 1) * 2 + 1];
                MMA_F16(acc[mt][nt], ah, b0, b1);
            }
        }
    }

    // ---- epilogue: dcov -> pow -> predicated direct store + sums -----------
    float diA[8], djB[8];
#pragma unroll
    for (int mt = 0; mt < 4; ++mt) {
        diA[mt * 2 + 0] = g_diag[b * DIM + ti * 128 + wm * 64 + mt * 16 + g];
        diA[mt * 2 + 1] = g_diag[b * DIM + ti * 128 + wm * 64 + mt * 16 + g + 8];
    }
#pragma unroll
    for (int nt = 0; nt < 4; ++nt) {
        djB[nt * 2 + 0] = g_diag[b * DIM + tj * 128 + wn * 32 + nt * 8 + tg * 2];
        djB[nt * 2 + 1] = g_diag[b * DIM + tj * 128 + wn * 32 + nt * 8 + tg * 2 + 1];
    }

    float* outb = out + (size_t)b * TRIU_PER_B;
    float r8[8], c8[8];
#pragma unroll
    for (int k = 0; k < 8; ++k) { r8[k] = 0.f; c8[k] = 0.f; }

#pragma unroll
    for (int mt = 0; mt < 4; ++mt) {
        int gi0 = ti * 128 + wm * 64 + mt * 16 + g;
        int gi1 = gi0 + 8;
        int rb0 = gi0 * DIM - (gi0 * (gi0 - 1)) / 2 - gi0;
        int rb1 = gi1 * DIM - (gi1 * (gi1 - 1)) / 2 - gi1;
#pragma unroll
        for (int nt = 0; nt < 4; ++nt) {
            if (skipF[mt][nt]) continue;
            int gj0 = tj * 128 + wn * 32 + nt * 8 + tg * 2;
            int gj1 = gj0 + 1;
            float v00, v01, v10, v11;
            {
                float gv = acc[mt][nt][0] * INV2M;
                float dc = fmaxf(diA[mt*2] + djB[nt*2] - 2.f*gv, 0.f) + EPS_C;
                v00 = (gi0 == gj0) ? DIAG_V : exp2f(ALPHA_C * __log2f(dc));
            }
            {
                float gv = acc[mt][nt][1] * INV2M;
                float dc = fmaxf(diA[mt*2] + djB[nt*2+1] - 2.f*gv, 0.f) + EPS_C;
                v01 = (gi0 == gj1) ? DIAG_V : exp2f(ALPHA_C * __log2f(dc));
            }
            {
                float gv = acc[mt][nt][2] * INV2M;
                float dc = fmaxf(diA[mt*2+1] + djB[nt*2] - 2.f*gv, 0.f) + EPS_C;
                v10 = (gi1 == gj0) ? DIAG_V : exp2f(ALPHA_C * __log2f(dc));
            }
            {
                float gv = acc[mt][nt][3] * INV2M;
                float dc = fmaxf(diA[mt*2+1] + djB[nt*2+1] - 2.f*gv, 0.f) + EPS_C;
                v11 = (gi1 == gj1) ? DIAG_V : exp2f(ALPHA_C * __log2f(dc));
            }
            if (gj0 >= gi0) outb[rb0 + gj0] = v00;
            if (gj1 >= gi0) outb[rb0 + gj1] = v01;
            if (gj0 >= gi1) outb[rb1 + gj0] = v10;
            if (gj1 >= gi1) outb[rb1 + gj1] = v11;
            r8[mt*2+0] += ((gj0 >= gi0) ? v00 : 0.f) + ((gj1 >= gi0) ? v01 : 0.f);
            r8[mt*2+1] += ((gj0 >= gi1) ? v10 : 0.f) + ((gj1 >= gi1) ? v11 : 0.f);
            c8[nt*2+0] += ((gj0 > gi0) ? v00 : 0.f) + ((gj0 > gi1) ? v10 : 0.f);
            c8[nt*2+1] += ((gj1 > gi0) ? v01 : 0.f) + ((gj1 > gi1) ? v11 : 0.f);
        }
    }

    // row partials: reduce over tg (lane bits 0,1)
#pragma unroll
    for (int k = 0; k < 8; ++k) {
        r8[k] += __shfl_xor_sync(0xffffffffu, r8[k], 1);
        r8[k] += __shfl_xor_sync(0xffffffffu, r8[k], 2);
    }
    if (tg == 0) {
#pragma unroll
        for (int k = 0; k < 8; ++k)
            atomicAdd(&rAcc[wm * 64 + (k >> 1) * 16 + g + (k & 1) * 8], r8[k]);
    }
    // col partials: reduce over g (lane bits 2,3,4)
#pragma unroll
    for (int k = 0; k < 8; ++k) {
        c8[k] += __shfl_xor_sync(0xffffffffu, c8[k], 4);
        c8[k] += __shfl_xor_sync(0xffffffffu, c8[k], 8);
        c8[k] += __shfl_xor_sync(0xffffffffu, c8[k], 16);
    }
    if (g == 0) {
#pragma unroll
        for (int k = 0; k < 8; ++k)
            atomicAdd(&cAcc[wn * 32 + (k >> 1) * 8 + tg * 2 + (k & 1)], c8[k]);
    }
    __syncthreads();

    if (tid < 128) {
        atomicAdd(&g_rowsum[b * DIM + ti * 128 + tid], rAcc[tid]);
        atomicAdd(&g_rowsum[b * DIM + tj * 128 + tid], cAcc[tid]);
    }
}

// ---------------------------------------------------------------------------
// Kernel 3: finalize per-batch means
// ---------------------------------------------------------------------------
__global__ void k_means() {
    int b = blockIdx.x, tid = threadIdx.x;
    __shared__ float red[256];
    float s = 0.f;
    for (int i = tid; i < DIM; i += 256) {
        float rs = g_rowsum[b * DIM + i];
        g_rmean[b * DIM + i] = rs * (1.0f / DIM);
        s += rs;
    }
    red[tid] = s;
    __syncthreads();
    for (int o = 128; o; o >>= 1) {
        if (tid < o) red[tid] += red[tid + o];
        __syncthreads();
    }
    if (tid == 0) g_tot[b] = red[0] * (1.0f / ((float)DIM * (float)DIM));
}

// ---------------------------------------------------------------------------
// Kernel 4: flat float4 double-centering with sqrt-based row inversion.
// ---------------------------------------------------------------------------
__device__ __forceinline__ int rb_of(int i) { return (i * (2 * DIM + 1 - i)) >> 1; }

__global__ void k_center(float* __restrict__ out) {
    int idx = blockIdx.x * blockDim.x + threadIdx.x;   // float4 index
    int b  = idx / (TRIU_PER_B / 4);
    int p  = (idx - b * (TRIU_PER_B / 4)) * 4;
    float arg = (float)(4198401 - 8 * p);
    int i = (int)((2049.0f - sqrtf(arg)) * 0.5f);
    if (i < 0) i = 0;
    if (i > DIM - 1) i = DIM - 1;
    while (i > 0 && rb_of(i) > p) --i;
    while (rb_of(i + 1) <= p) ++i;

    const float* rm = g_rmean + b * DIM;
    float tt = g_tot[b];
    float* ptr = out + (size_t)b * TRIU_PER_B + p;
    float4 v = *(float4*)ptr;
    float e[4] = {v.x, v.y, v.z, v.w};
    int ii = i;
#pragma unroll
    for (int k = 0; k < 4; ++k) {
        while (rb_of(ii + 1) <= p + k) ++ii;
        int j = p + k - rb_of(ii) + ii;
        e[k] = e[k] - rm[ii] - rm[j] + tt;
    }
    v.x = e[0]; v.y = e[1]; v.z = e[2]; v.w = e[3];
    *(float4*)ptr = v;
}

// ---------------------------------------------------------------------------
extern "C" void kernel_launch(void* const* d_in, const int* in_sizes, int n_in,
                              void* d_out, int out_size) {
    (void)in_sizes; (void)n_in; (void)out_size;
    const float* x = (const float*)d_in[0];
    float* out = (float*)d_out;

    cudaFuncSetAttribute(k_main, cudaFuncAttributeMaxDynamicSharedMemorySize,
                         SMEM_MAIN);

    k_half<<<(BATCH * DIM) / 8, 256>>>(x);
    k_main<<<BATCH * NTRI, 256, SMEM_MAIN>>>(out);
    k_means<<<BATCH, 256>>>();
    k_center<<<(BATCH * TRIU_PER_B / 4) / 256, 256>>>(out);
}